// round 6
// baseline (speedup 1.0000x reference)
#include <cuda_runtime.h>
#include <cstdint>

#define GS     256
#define NCLS   10
#define NPTS   262144            // 2^18
#define BATCH  16
#define CELLS  (GS * GS)         // 65536
#define TCELLS (BATCH * CELLS)   // 1,048,576
#define PTOT   (BATCH * NPTS)    // 4,194,304
#define CAP    16                // bucket capacity per cell (Poisson(4): P(>16) ~ 1e-6)
#define IMGS   (BATCH * NCLS)    // 160
#define OUTN   (IMGS * CELLS)    // 10,485,760 floats

// ---------------------------------------------------------------------------
// Scratch (device globals: allocation-free per harness rules)
// payA: v0..v7  (32B records, sector-aligned -> scattered writes = 1 full sector)
// payB: v8,v9,rx,ry (16B records, half-sector)
// ---------------------------------------------------------------------------
__device__ uint32_t g_cursor[TCELLS];
__device__ __align__(128) float4 g_payA[(size_t)TCELLS * CAP * 2];  // 512 MB
__device__ __align__(128) float4 g_payB[(size_t)TCELLS * CAP];      // 256 MB

// ---------------------------------------------------------------------------
// Zero d_out (float4) + g_cursor (uint4)
// ---------------------------------------------------------------------------
#define OUT4  (OUTN / 4)       // 2,621,440
#define CUR4  (TCELLS / 4)     // 262,144
__global__ __launch_bounds__(256)
void zero_kernel(float4* __restrict__ out) {
    const int i = blockIdx.x * blockDim.x + threadIdx.x;
    if (i < OUT4) {
        out[i] = make_float4(0.f, 0.f, 0.f, 0.f);
    } else if (i < OUT4 + CUR4) {
        ((uint4*)g_cursor)[i - OUT4] = make_uint4(0u, 0u, 0u, 0u);
    }
}

// ---------------------------------------------------------------------------
// Pass A: scatter into fixed-capacity buckets; rare overflow -> direct atomics
// Launched twice with half the points each (gid0 offset) so launch idx 3 is
// reduce_kernel (ncu capture slot).
// ---------------------------------------------------------------------------
__global__ __launch_bounds__(256)
void scatter_kernel(const float* __restrict__ points,
                    const float* __restrict__ values,
                    float* __restrict__ out,
                    int gid0) {
    const int gid = gid0 + blockIdx.x * blockDim.x + threadIdx.x;
    const int b = gid >> 18;
    const int n = gid & (NPTS - 1);

    const float* pb = points + (size_t)b * 2 * NPTS;
    const float fx = (pb[n] + 0.5f) * (float)GS;
    const float fy = (pb[NPTS + n] + 0.5f) * (float)GS;
    const float xf = floorf(fx);
    const float yf = floorf(fy);
    const int x = (int)xf;
    const int y = (int)yf;
    const float rx = fx - xf;
    const float ry = fy - yf;
    if (((unsigned)x >= GS) || ((unsigned)y >= GS)) return;  // contributes nothing

    // start value loads first (independent of the atomic's 318-cyc return)
    const float* vb = values + (size_t)b * NCLS * NPTS + n;
    float v[10];
#pragma unroll
    for (int c = 0; c < NCLS; c++) v[c] = vb[(size_t)c * NPTS];  // coalesced per class

    const int cellg = (b << 16) + (y << 8) + x;
    const uint32_t slot = atomicAdd(&g_cursor[cellg], 1u);

    if (slot < CAP) {
        const size_t sA = ((size_t)cellg * CAP + slot) * 2;
        __stcs(&g_payA[sA + 0], make_float4(v[0], v[1], v[2], v[3]));
        __stcs(&g_payA[sA + 1], make_float4(v[4], v[5], v[6], v[7]));
        __stcs(&g_payB[(size_t)cellg * CAP + slot], make_float4(v[8], v[9], rx, ry));
    } else {
        // overflow (expected ~a few points per run): direct CIC atomics into out
        const bool vx1 = (x + 1) < GS;
        const bool vy1 = (y + 1) < GS;
        const float wx0 = 1.f - rx, wy0 = 1.f - ry;
        const float w00 = wx0 * wy0, w10 = rx * wy0, w01 = wx0 * ry, w11 = rx * ry;
        const int i00 = (y << 8) + x;
        float* ob = out + (size_t)b * NCLS * CELLS;
#pragma unroll
        for (int c = 0; c < NCLS; c++) {
            float* o = ob + ((size_t)c << 16);
            atomicAdd(o + i00, w00 * v[c]);
            if (vx1)        atomicAdd(o + i00 + 1,      w10 * v[c]);
            if (vy1)        atomicAdd(o + i00 + GS,     w01 * v[c]);
            if (vx1 && vy1) atomicAdd(o + i00 + GS + 1, w11 * v[c]);
        }
    }
}

// ---------------------------------------------------------------------------
// Pass B: fused reduce + corner-combine, one THREAD per CELL.
// Block = 16x16 cell tile, 256 threads, 40 register accumulators per thread.
// Interior patch positions: non-atomic RMW (preserves overflow atomics).
// Shared border frame: atomicAdd.
// ---------------------------------------------------------------------------
__global__ __launch_bounds__(256)
void reduce_kernel(float* __restrict__ out) {
    const int t = threadIdx.x;
    const int ly = t >> 4;
    const int lx = t & 15;

    const int blk = blockIdx.x;        // 0..4095
    const int b  = blk >> 8;
    const int tt = blk & 255;
    const int ty = tt >> 4;            // tile row 0..15
    const int tx = tt & 15;            // tile col 0..15

    const int cellg = (b << 16) + ((ty * 16 + ly) << 8) + (tx * 16 + lx);
    const uint32_t raw = g_cursor[cellg];
    const uint32_t cnt = raw < CAP ? raw : CAP;

    float acc[4][NCLS];
#pragma unroll
    for (int k = 0; k < 4; k++)
#pragma unroll
        for (int c = 0; c < NCLS; c++) acc[k][c] = 0.f;

    const size_t baseA = (size_t)cellg * CAP * 2;
    const size_t baseB = (size_t)cellg * CAP;
    for (uint32_t i = 0; i < cnt; i++) {
        const float4 a  = __ldcs(&g_payA[baseA + (size_t)i * 2 + 0]);
        const float4 bq = __ldcs(&g_payA[baseA + (size_t)i * 2 + 1]);
        const float4 cq = __ldcs(&g_payB[baseB + i]);
        const float rx = cq.z, ry = cq.w;
        const float wx0 = 1.f - rx, wy0 = 1.f - ry;
        const float w00 = wx0 * wy0, w10 = rx * wy0, w01 = wx0 * ry, w11 = rx * ry;
        const float v[10] = {a.x, a.y, a.z, a.w, bq.x, bq.y, bq.z, bq.w, cq.x, cq.y};
#pragma unroll
        for (int c = 0; c < NCLS; c++) {
            acc[0][c] += w00 * v[c];
            acc[1][c] += w10 * v[c];
            acc[2][c] += w01 * v[c];
            acc[3][c] += w11 * v[c];
        }
    }

    // stage: st[corner][class][cell] (stride-1 in cell -> conflict-free)
    __shared__ float st[4][NCLS][256];
#pragma unroll
    for (int k = 0; k < 4; k++)
#pragma unroll
        for (int c = 0; c < NCLS; c++) st[k][c][t] = acc[k][c];
    __syncthreads();

    // assemble 17x17 patch per class: 2890 outputs over 256 threads
    for (int w = t; w < 17 * 17 * NCLS; w += 256) {
        const int c2 = w / 289;
        const int r  = w - 289 * c2;
        const int oy = r / 17;
        const int ox = r - 17 * oy;

        float v = 0.f;
        if (oy < 16 && ox < 16)   v += st[0][c2][oy * 16 + ox];
        if (oy < 16 && ox >= 1)   v += st[1][c2][oy * 16 + ox - 1];
        if (oy >= 1 && ox < 16)   v += st[2][c2][(oy - 1) * 16 + ox];
        if (oy >= 1 && ox >= 1)   v += st[3][c2][(oy - 1) * 16 + ox - 1];

        const int Y = ty * 16 + oy;
        const int X = tx * 16 + ox;
        if (Y > 255 || X > 255) continue;

        float* dst = out + (((size_t)(b * NCLS + c2)) << 16) + (Y << 8) + X;
        const bool excl = (oy != 16) && (ox != 16) &&
                          (oy != 0 || ty == 0) && (ox != 0 || tx == 0);
        if (excl) *dst = v + *dst;      // plain RMW keeps overflow contributions
        else      atomicAdd(dst, v);
    }
}

// ---------------------------------------------------------------------------
// Harness entry: d_in[0]=points [16,2,262144] f32, d_in[1]=values [16,10,262144] f32
// d_out = [16,10,256,256] f32
// Scatter split into two half launches so 0-based launch idx 3 = reduce
// (that's the launch ncu captures).
// ---------------------------------------------------------------------------
extern "C" void kernel_launch(void* const* d_in, const int* in_sizes, int n_in,
                              void* d_out, int out_size) {
    const float* points = (const float*)d_in[0];
    const float* values = (const float*)d_in[1];
    float* out = (float*)d_out;

    const int half = PTOT / 2;
    zero_kernel<<<(OUT4 + CUR4 + 255) / 256, 256>>>((float4*)out);
    scatter_kernel<<<half / 256, 256>>>(points, values, out, 0);
    scatter_kernel<<<half / 256, 256>>>(points, values, out, half);
    reduce_kernel<<<TCELLS / 256, 256>>>(out);
}

// round 7
// speedup vs baseline: 1.2273x; 1.2273x over previous
#include <cuda_runtime.h>
#include <cstdint>

#define GS     256
#define NCLS   10
#define NPTS   262144            // 2^18
#define BATCH  16
#define CELLS  (GS * GS)         // 65536
#define TCELLS (BATCH * CELLS)   // 1,048,576
#define PTOT   (BATCH * NPTS)    // 4,194,304
#define CAP    16                // bucket capacity per cell (Poisson(4): P(>16) ~ 1e-6)
#define IMGS   (BATCH * NCLS)    // 160
#define OUTN   (IMGS * CELLS)    // 10,485,760 floats

// ---------------------------------------------------------------------------
// Scratch — SLOT-MAJOR buckets: records for slot i of all cells are contiguous,
// so the reduce (lane = consecutive cell) reads coalesced runs.
//   payA[slot][cell] : v0..v7  (two float4 = 32B, 32B-aligned)
//   payB[slot][cell] : v8,v9,rx,ry (one float4 = 16B)
// ---------------------------------------------------------------------------
__device__ uint32_t g_cursor[TCELLS];
__device__ __align__(128) float4 g_payA[(size_t)CAP * TCELLS * 2];  // 512 MB
__device__ __align__(128) float4 g_payB[(size_t)CAP * TCELLS];      // 256 MB

// ---------------------------------------------------------------------------
// Zero kernels (3 launches so scatter sits at ncu's capture slot, idx 3)
// ---------------------------------------------------------------------------
#define OUT4  (OUTN / 4)       // 2,621,440
#define CUR4  (TCELLS / 4)     // 262,144
__global__ __launch_bounds__(256)
void zero_range_kernel(float4* __restrict__ p, int n4) {
    const int i = blockIdx.x * blockDim.x + threadIdx.x;
    if (i < n4) p[i] = make_float4(0.f, 0.f, 0.f, 0.f);
}
__global__ __launch_bounds__(256)
void zero_cursor_kernel() {
    const int i = blockIdx.x * blockDim.x + threadIdx.x;
    if (i < CUR4) ((uint4*)g_cursor)[i] = make_uint4(0u, 0u, 0u, 0u);
}

// ---------------------------------------------------------------------------
// Pass A: scatter into fixed-capacity slot-major buckets; overflow -> atomics
// ---------------------------------------------------------------------------
__global__ __launch_bounds__(256)
void scatter_kernel(const float* __restrict__ points,
                    const float* __restrict__ values,
                    float* __restrict__ out) {
    const int gid = blockIdx.x * blockDim.x + threadIdx.x;
    const int b = gid >> 18;
    const int n = gid & (NPTS - 1);

    const float* pb = points + (size_t)b * 2 * NPTS;
    const float fx = (pb[n] + 0.5f) * (float)GS;
    const float fy = (pb[NPTS + n] + 0.5f) * (float)GS;
    const float xf = floorf(fx);
    const float yf = floorf(fy);
    const int x = (int)xf;
    const int y = (int)yf;
    const float rx = fx - xf;
    const float ry = fy - yf;
    if (((unsigned)x >= GS) || ((unsigned)y >= GS)) return;  // contributes nothing

    // start value loads before the atomic (overlap the ~318-cyc ATOMG return)
    const float* vb = values + (size_t)b * NCLS * NPTS + n;
    float v[10];
#pragma unroll
    for (int c = 0; c < NCLS; c++) v[c] = vb[(size_t)c * NPTS];  // coalesced per class

    const int cellg = (b << 16) + (y << 8) + x;
    const uint32_t slot = atomicAdd(&g_cursor[cellg], 1u);

    if (slot < CAP) {
        const size_t rec = (size_t)slot * TCELLS + cellg;
        __stcs(&g_payA[rec * 2 + 0], make_float4(v[0], v[1], v[2], v[3]));
        __stcs(&g_payA[rec * 2 + 1], make_float4(v[4], v[5], v[6], v[7]));
        __stcs(&g_payB[rec],         make_float4(v[8], v[9], rx, ry));
    } else {
        // overflow (expected ~a few points per run): direct CIC atomics into out
        const bool vx1 = (x + 1) < GS;
        const bool vy1 = (y + 1) < GS;
        const float wx0 = 1.f - rx, wy0 = 1.f - ry;
        const float w00 = wx0 * wy0, w10 = rx * wy0, w01 = wx0 * ry, w11 = rx * ry;
        const int i00 = (y << 8) + x;
        float* ob = out + (size_t)b * NCLS * CELLS;
#pragma unroll
        for (int c = 0; c < NCLS; c++) {
            float* o = ob + ((size_t)c << 16);
            atomicAdd(o + i00, w00 * v[c]);
            if (vx1)        atomicAdd(o + i00 + 1,      w10 * v[c]);
            if (vy1)        atomicAdd(o + i00 + GS,     w01 * v[c]);
            if (vx1 && vy1) atomicAdd(o + i00 + GS + 1, w11 * v[c]);
        }
    }
}

// ---------------------------------------------------------------------------
// Pass B: fused reduce + corner-combine, one THREAD per CELL.
// Slot-major layout -> iteration i reads coalesced runs across the warp.
// Warp-uniform trip count with per-lane predication.
// ---------------------------------------------------------------------------
__global__ __launch_bounds__(256)
void reduce_kernel(float* __restrict__ out) {
    const int t = threadIdx.x;
    const int ly = t >> 4;
    const int lx = t & 15;

    const int blk = blockIdx.x;        // 0..4095
    const int b  = blk >> 8;
    const int tt = blk & 255;
    const int ty = tt >> 4;            // tile row 0..15
    const int tx = tt & 15;            // tile col 0..15

    const int cellg = (b << 16) + ((ty * 16 + ly) << 8) + (tx * 16 + lx);
    const uint32_t raw = g_cursor[cellg];
    const uint32_t cnt = raw < CAP ? raw : CAP;
    const uint32_t wmax = __reduce_max_sync(0xFFFFFFFFu, cnt);

    float acc[4][NCLS];
#pragma unroll
    for (int k = 0; k < 4; k++)
#pragma unroll
        for (int c = 0; c < NCLS; c++) acc[k][c] = 0.f;

    for (uint32_t i = 0; i < wmax; i++) {
        if (i < cnt) {
            const size_t rec = (size_t)i * TCELLS + cellg;
            const float4 a  = __ldcs(&g_payA[rec * 2 + 0]);
            const float4 bq = __ldcs(&g_payA[rec * 2 + 1]);
            const float4 cq = __ldcs(&g_payB[rec]);
            const float rx = cq.z, ry = cq.w;
            const float wx0 = 1.f - rx, wy0 = 1.f - ry;
            const float w00 = wx0 * wy0, w10 = rx * wy0, w01 = wx0 * ry, w11 = rx * ry;
            const float v[10] = {a.x, a.y, a.z, a.w, bq.x, bq.y, bq.z, bq.w, cq.x, cq.y};
#pragma unroll
            for (int c = 0; c < NCLS; c++) {
                acc[0][c] += w00 * v[c];
                acc[1][c] += w10 * v[c];
                acc[2][c] += w01 * v[c];
                acc[3][c] += w11 * v[c];
            }
        }
    }

    // stage: st[corner][class][cell] (stride-1 in cell -> conflict-free)
    __shared__ float st[4][NCLS][256];
#pragma unroll
    for (int k = 0; k < 4; k++)
#pragma unroll
        for (int c = 0; c < NCLS; c++) st[k][c][t] = acc[k][c];
    __syncthreads();

    // assemble 17x17 patch per class: 2890 outputs over 256 threads
    for (int w = t; w < 17 * 17 * NCLS; w += 256) {
        const int c2 = w / 289;
        const int r  = w - 289 * c2;
        const int oy = r / 17;
        const int ox = r - 17 * oy;

        float v = 0.f;
        if (oy < 16 && ox < 16)   v += st[0][c2][oy * 16 + ox];
        if (oy < 16 && ox >= 1)   v += st[1][c2][oy * 16 + ox - 1];
        if (oy >= 1 && ox < 16)   v += st[2][c2][(oy - 1) * 16 + ox];
        if (oy >= 1 && ox >= 1)   v += st[3][c2][(oy - 1) * 16 + ox - 1];

        const int Y = ty * 16 + oy;
        const int X = tx * 16 + ox;
        if (Y > 255 || X > 255) continue;

        float* dst = out + (((size_t)(b * NCLS + c2)) << 16) + (Y << 8) + X;
        const bool excl = (oy != 16) && (ox != 16) &&
                          (oy != 0 || ty == 0) && (ox != 0 || tx == 0);
        if (excl) *dst = v + *dst;      // plain RMW keeps overflow contributions
        else      atomicAdd(dst, v);
    }
}

// ---------------------------------------------------------------------------
// Harness entry: d_in[0]=points [16,2,262144] f32, d_in[1]=values [16,10,262144] f32
// d_out = [16,10,256,256] f32
// Launch order puts scatter at idx 3 (ncu capture slot).
// ---------------------------------------------------------------------------
extern "C" void kernel_launch(void* const* d_in, const int* in_sizes, int n_in,
                              void* d_out, int out_size) {
    const float* points = (const float*)d_in[0];
    const float* values = (const float*)d_in[1];
    float* out = (float*)d_out;

    const int h4 = OUT4 / 2;
    zero_range_kernel<<<(h4 + 255) / 256, 256>>>((float4*)out, h4);                 // idx 0
    zero_range_kernel<<<(h4 + 255) / 256, 256>>>((float4*)out + h4, OUT4 - h4);     // idx 1
    zero_cursor_kernel<<<(CUR4 + 255) / 256, 256>>>();                               // idx 2
    scatter_kernel<<<PTOT / 256, 256>>>(points, values, out);                        // idx 3 (profiled)
    reduce_kernel<<<TCELLS / 256, 256>>>(out);                                       // idx 4
}